// round 12
// baseline (speedup 1.0000x reference)
#include <cuda_runtime.h>
#include <cuda_fp16.h>
#include <stdint.h>

#define NN 50000
#define EE 800000
#define RR 8
#define BB 8
#define HH 128
#define LL 3
#define FDIM 6
#define KTOT 1152          // R*H + H (root folded in)
#define NSEG (NN * RR)     // 400000
#define NBLK 391           // ceil(NSEG/1024)
#define BN_EPS 1e-5f
#define NST 3              // GEMM pipeline stages (R9 measured-good config)
#define KC 64              // K-chunk in halves (128B rows)
#define NKT (KTOT / KC)    // 18 chunks
#define STAGE_BYTES 32768  // A 16KB + B 16KB

// ---------------- scratch (static device memory) ----------------------------
// Tiled + pre-swizzled A: [chunk][n][64 halves]; element (n,k) at plane k/64,
// row n, byte ((k&63)*2) ^ ((n&7)<<4).  Chunks 0..15 = seg means, 16..17 = x.
__device__ __half g_A[(size_t)NKT * NN * KC + 8192];   // 115.2 MB + pad
__device__ __half g_WhT[NKT * HH * KC];                // tiled+swizzled W
__device__ float  g_h[NN * HH];                        // pre-BN layer output
__device__ int    g_cnt[NSEG];
__device__ int    g_off[NSEG + 1];                     // block-local exclusive partials
__device__ int    g_cursor[NSEG];
__device__ int    g_bsum[512];                         // exclusive block offsets
__device__ int    g_src[EE];
__device__ double g_sum[HH], g_sumsq[HH];

// ---------------- PTX helpers -------------------------------------------------
#define MBARRIER_INIT(addr, cnt) \
    asm volatile("mbarrier.init.shared.b64 [%0], %1;" :: "r"(addr), "r"(cnt) : "memory")
#define MBARRIER_EXPECT_TX(addr, bytes) \
    asm volatile("mbarrier.arrive.expect_tx.shared.b64 _, [%0], %1;" \
                 :: "r"(addr), "r"(bytes) : "memory")
#define MBARRIER_WAIT_PARITY(addr, par) do {                                   \
    asm volatile(                                                              \
        "{\n\t.reg .pred P1;\n\t"                                              \
        "WAIT_LOOP_%=:\n\t"                                                    \
        "mbarrier.try_wait.parity.acquire.cta.shared::cta.b64 P1, [%0], %1, 0x989680;\n\t" \
        "@P1 bra.uni WAIT_DONE_%=;\n\t"                                        \
        "bra.uni WAIT_LOOP_%=;\n\t"                                            \
        "WAIT_DONE_%=:\n\t}"                                                   \
        :: "r"(addr), "r"(par) : "memory");                                    \
} while (0)
#define BULK_G2S(dst_u32, src, bytes, mbar) \
    asm volatile("cp.async.bulk.shared::cluster.global.mbarrier::complete_tx::bytes " \
                 "[%0], [%1], %2, [%3];" \
                 :: "r"(dst_u32), "l"(src), "r"(bytes), "r"(mbar) : "memory")

// swizzled byte-offset within a 128B row
__device__ __forceinline__ uint32_t swz(int row, int hcol) {
    return (uint32_t)((hcol * 2) ^ ((row & 7) << 4));
}

// ---------------- init / CSR build ------------------------------------------

__global__ void init_x_kernel(float* __restrict__ x,
                              const int* __restrict__ x_ids,
                              const float* __restrict__ node_feat,
                              const float* __restrict__ emb,
                              const float* __restrict__ feat_w,
                              const float* __restrict__ feat_b,
                              const float* __restrict__ virt) {
    int n = blockIdx.x, o = threadIdx.x;
    int gt = blockIdx.x * blockDim.x + threadIdx.x;
    if (gt < NSEG) g_cnt[gt] = 0;
    float f = feat_b[o];
#pragma unroll
    for (int d = 0; d < FDIM; d++)
        f += node_feat[n * FDIM + d] * feat_w[o * FDIM + d];
    float v = emb[x_ids[n] * HH + o] + fmaxf(f, 0.f) + virt[o];
    x[n * HH + o] = v;
    int c = 16 + (o >> 6);
    char* p = (char*)g_A + ((size_t)c * NN + n) * 128 + swz(n, o & 63);
    *(__half*)p = __float2half(v);
}

__global__ void count_edges_kernel(const int* __restrict__ edge_index,
                                   const int* __restrict__ edge_type) {
    int e = blockIdx.x * blockDim.x + threadIdx.x;
    if (e >= EE) return;
    atomicAdd(&g_cnt[edge_index[EE + e] * RR + edge_type[e]], 1);
}

__global__ void scan_block_kernel() {
    __shared__ int sm[1024];
    int i = blockIdx.x * 1024 + threadIdx.x;
    int v = (i < NSEG) ? g_cnt[i] : 0;
    sm[threadIdx.x] = v;
    __syncthreads();
    for (int s = 1; s < 1024; s <<= 1) {
        int t = (threadIdx.x >= s) ? sm[threadIdx.x - s] : 0;
        __syncthreads();
        sm[threadIdx.x] += t;
        __syncthreads();
    }
    if (i < NSEG) {
        int o = sm[threadIdx.x] - v;     // block-local exclusive
        g_off[i] = o;
        g_cursor[i] = o;
    }
    if (threadIdx.x == 1023) g_bsum[blockIdx.x] = sm[1023];
}

__global__ void scan_sums_kernel() {
    __shared__ int sm[512];
    int v = (threadIdx.x < NBLK) ? g_bsum[threadIdx.x] : 0;
    sm[threadIdx.x] = v;
    __syncthreads();
    for (int s = 1; s < 512; s <<= 1) {
        int t = (threadIdx.x >= s) ? sm[threadIdx.x - s] : 0;
        __syncthreads();
        sm[threadIdx.x] += t;
        __syncthreads();
    }
    g_bsum[threadIdx.x] = sm[threadIdx.x] - v;   // exclusive block offsets
}

// final position = local cursor + block offset (same final layout as before)
__global__ void csr_fill_kernel(const int* __restrict__ edge_index,
                                const int* __restrict__ edge_type) {
    int e = blockIdx.x * blockDim.x + threadIdx.x;
    if (e >= EE) return;
    int seg = edge_index[EE + e] * RR + edge_type[e];
    int pos = atomicAdd(&g_cursor[seg], 1) + g_bsum[seg >> 10];
    g_src[pos] = edge_index[e];
}

// ---------------- per-layer kernels -----------------------------------------

// W tiled+swizzled + zero BN stats.
__global__ void build_W_kernel(const float* __restrict__ comp,
                               const float* __restrict__ bases,
                               const float* __restrict__ root, int l) {
    int o = blockIdx.x;
    if (threadIdx.x == 0) { g_sum[o] = 0.0; g_sumsq[o] = 0.0; }
    for (int k = threadIdx.x; k < KTOT; k += blockDim.x) {
        float acc;
        if (k < RR * HH) {
            int r = k >> 7, i = k & 127;
            acc = 0.f;
#pragma unroll
            for (int b = 0; b < BB; b++)
                acc += comp[(l * RR + r) * BB + b] *
                       bases[((l * BB + b) * HH + i) * HH + o];
        } else {
            acc = root[(l * HH + (k - RR * HH)) * HH + o];
        }
        int c = k >> 6;
        char* p = (char*)g_WhT + ((size_t)c * HH + o) * 128 + swz(o, k & 63);
        *(__half*)p = __float2half(acc);
    }
}

// warp-per-segment gather-sum; reads x planes (16,17), writes mean planes (2r, 2r+1).
__global__ void seg_sum_kernel() {
    int seg = blockIdx.x * 8 + (threadIdx.x >> 5);
    if (seg >= NSEG) return;
    int lane = threadIdx.x & 31;
    int cx = 16 + (lane >> 4);               // source x plane for this lane
    uint32_t bcol = (uint32_t)((lane & 15) * 8);
    int beg = g_off[seg] + g_bsum[seg >> 10];
    int cnt = g_cnt[seg];
    int end = beg + cnt;
    float a0 = 0.f, a1 = 0.f, a2 = 0.f, a3 = 0.f;
    const char* xbase = (const char*)g_A + (size_t)cx * NN * 128;
    for (int e = beg; e < end; e++) {
        int src = g_src[e];
        uint2 v = *(const uint2*)(xbase + (size_t)src * 128 + (bcol ^ ((src & 7) << 4)));
        float2 f0 = __half22float2(*(__half2*)&v.x);
        float2 f1 = __half22float2(*(__half2*)&v.y);
        a0 += f0.x; a1 += f0.y; a2 += f1.x; a3 += f1.y;
    }
    float inv = (cnt > 0) ? 1.f / (float)cnt : 0.f;
    __half2 o0 = __floats2half2_rn(a0 * inv, a1 * inv);
    __half2 o1 = __floats2half2_rn(a2 * inv, a3 * inv);
    uint2 o;
    o.x = *(unsigned*)&o0;
    o.y = *(unsigned*)&o1;
    int n = seg >> 3, r = seg & 7;
    int cd = 2 * r + (lane >> 4);
    char* dst = (char*)g_A + ((size_t)cd * NN + n) * 128 + (bcol ^ ((n & 7) << 4));
    *(uint2*)dst = o;
}

// GEMM: g_h = A[50000 x 1152] * W[1152 x 128] + bias, BN stats fused.
// Bulk-async loads (2 per stage), 3 stages, mma.sync m16n8k16 fp32-acc.
// Identical to the R9 measured-good configuration.
__global__ void __launch_bounds__(256) gemm_kernel(const float* __restrict__ bias) {
    extern __shared__ __align__(1024) char dynsm[];
    uint32_t smem_base;
    asm("{ .reg .u64 t; cvta.to.shared.u64 t, %1; cvt.u32.u64 %0, t; }"
        : "=r"(smem_base) : "l"(dynsm));
    const uint32_t MBAR = smem_base;           // 3 x 8B
    float* red = (float*)(dynsm + 64);          // [2][128][2] = 2KB
    char* stages = dynsm + 4096;
    const uint32_t STAGES_U32 = smem_base + 4096;

    int tid = threadIdx.x;
    int warp = tid >> 5, lane = tid & 31;
    int warp_m = warp >> 2, warp_n = warp & 3;   // 2 x 4 warps
    int m0 = blockIdx.x * 128;
    int gr = lane >> 2, tc = lane & 3;

    if (tid == 0) {
#pragma unroll
        for (int s = 0; s < NST; s++) MBARRIER_INIT(MBAR + s * 8, 1);
    }
    __syncthreads();

    // prologue: issue chunks 0..NST-1
    if (tid == 0) {
#pragma unroll
        for (int s = 0; s < NST; s++) {
            MBARRIER_EXPECT_TX(MBAR + s * 8, STAGE_BYTES);
            const char* srcA = (const char*)g_A + ((size_t)s * NN + m0) * 128;
            const char* srcB = (const char*)g_WhT + (size_t)s * HH * 128;
            BULK_G2S(STAGES_U32 + s * STAGE_BYTES, srcA, 16384, MBAR + s * 8);
            BULK_G2S(STAGES_U32 + s * STAGE_BYTES + 16384, srcB, 16384, MBAR + s * 8);
        }
    }

    float acc[4][4][4];
#pragma unroll
    for (int a = 0; a < 4; a++)
#pragma unroll
        for (int b = 0; b < 4; b++)
#pragma unroll
            for (int c = 0; c < 4; c++) acc[a][b][c] = 0.f;

    for (int t = 0; t < NKT; t++) {
        int s = t % NST;
        MBARRIER_WAIT_PARITY(MBAR + s * 8, (t / NST) & 1);

        const char* sA = stages + s * STAGE_BYTES;
        const char* sB = sA + 16384;
#pragma unroll
        for (int kk = 0; kk < KC; kk += 16) {
            int hc0 = kk + 2 * tc;
            unsigned bf[4][2];
#pragma unroll
            for (int nt = 0; nt < 4; nt++) {
                int n0 = warp_n * 32 + nt * 8 + gr;
                const char* bp = sB + n0 * 128;
                bf[nt][0] = *(const unsigned*)(bp + swz(n0, hc0));
                bf[nt][1] = *(const unsigned*)(bp + swz(n0, hc0 + 8));
            }
#pragma unroll
            for (int mt = 0; mt < 4; mt++) {
                int r0 = warp_m * 64 + mt * 16 + gr;
                const char* ap0 = sA + r0 * 128;
                const char* ap1 = sA + (r0 + 8) * 128;
                unsigned a0 = *(const unsigned*)(ap0 + swz(r0, hc0));
                unsigned a1 = *(const unsigned*)(ap1 + swz(r0 + 8, hc0));
                unsigned a2 = *(const unsigned*)(ap0 + swz(r0, hc0 + 8));
                unsigned a3 = *(const unsigned*)(ap1 + swz(r0 + 8, hc0 + 8));
#pragma unroll
                for (int nt = 0; nt < 4; nt++) {
                    asm volatile(
                        "mma.sync.aligned.m16n8k16.row.col.f32.f16.f16.f32 "
                        "{%0,%1,%2,%3}, {%4,%5,%6,%7}, {%8,%9}, {%0,%1,%2,%3};\n"
                        : "+f"(acc[mt][nt][0]), "+f"(acc[mt][nt][1]),
                          "+f"(acc[mt][nt][2]), "+f"(acc[mt][nt][3])
                        : "r"(a0), "r"(a1), "r"(a2), "r"(a3),
                          "r"(bf[nt][0]), "r"(bf[nt][1]));
                }
            }
        }
        __syncthreads();
        if (tid == 0 && t + NST < NKT) {
            int u = t + NST;
            MBARRIER_EXPECT_TX(MBAR + s * 8, STAGE_BYTES);
            const char* srcA = (const char*)g_A + ((size_t)u * NN + m0) * 128;
            const char* srcB = (const char*)g_WhT + (size_t)u * HH * 128;
            BULK_G2S(STAGES_U32 + s * STAGE_BYTES, srcA, 16384, MBAR + s * 8);
            BULK_G2S(STAGES_U32 + s * STAGE_BYTES + 16384, srcB, 16384, MBAR + s * 8);
        }
    }

    // epilogue: + bias, store fp32, BN stats
    float s4[4][2] = {}, q4[4][2] = {};
#pragma unroll
    for (int mt = 0; mt < 4; mt++) {
#pragma unroll
        for (int nt = 0; nt < 4; nt++) {
            int row = m0 + warp_m * 64 + mt * 16 + gr;
            int col = warp_n * 32 + nt * 8 + 2 * tc;
            float b0 = bias[col], b1 = bias[col + 1];
            if (row < NN) {
                float h0 = acc[mt][nt][0] + b0;
                float h1 = acc[mt][nt][1] + b1;
                g_h[row * HH + col] = h0;
                g_h[row * HH + col + 1] = h1;
                s4[nt][0] += h0; q4[nt][0] += h0 * h0;
                s4[nt][1] += h1; q4[nt][1] += h1 * h1;
            }
            if (row + 8 < NN) {
                float h2 = acc[mt][nt][2] + b0;
                float h3 = acc[mt][nt][3] + b1;
                g_h[(row + 8) * HH + col] = h2;
                g_h[(row + 8) * HH + col + 1] = h3;
                s4[nt][0] += h2; q4[nt][0] += h2 * h2;
                s4[nt][1] += h3; q4[nt][1] += h3 * h3;
            }
        }
    }
#pragma unroll
    for (int nt = 0; nt < 4; nt++) {
#pragma unroll
        for (int idx = 0; idx < 2; idx++) {
            float v = s4[nt][idx], w = q4[nt][idx];
#pragma unroll
            for (int off = 16; off >= 4; off >>= 1) {
                v += __shfl_down_sync(0xffffffffu, v, off);
                w += __shfl_down_sync(0xffffffffu, w, off);
            }
            if (gr == 0) {
                int col = warp_n * 32 + nt * 8 + 2 * tc + idx;
                red[(warp_m * 128 + col) * 2 + 0] = v;
                red[(warp_m * 128 + col) * 2 + 1] = w;
            }
        }
    }
    __syncthreads();
    if (tid < 128) {
        int col = tid;
        atomicAdd(&g_sum[col],   (double)(red[col * 2] + red[(128 + col) * 2]));
        atomicAdd(&g_sumsq[col], (double)(red[col * 2 + 1] + red[(128 + col) * 2 + 1]));
    }
}

// update: BN scale/shift computed per block (no separate bn_prep launch),
// 4 elements per thread. Grid 6250 x 256 covers NN*HH exactly.
__global__ void update_kernel(float* __restrict__ x,
                              const float* __restrict__ gamma,
                              const float* __restrict__ beta) {
    __shared__ float sc[HH], sh[HH];
    int t = threadIdx.x;
    if (t < HH) {
        const double invN = 1.0 / (double)NN;
        double mu = g_sum[t] * invN;
        double var = g_sumsq[t] * invN - mu * mu;
        float rstd = rsqrtf((float)var + BN_EPS);
        float s = gamma[t] * rstd;
        sc[t] = s;
        sh[t] = beta[t] - (float)mu * s;
    }
    __syncthreads();
    int idx = (blockIdx.x * 256 + t) * 4;
    int n = idx >> 7, o = idx & 127;
    float4 h4 = *(const float4*)(g_h + idx);
    float4 x4 = *(float4*)(x + idx);
    float r0 = x4.x + fmaxf(fmaf(h4.x, sc[o],     sh[o]),     0.f);
    float r1 = x4.y + fmaxf(fmaf(h4.y, sc[o + 1], sh[o + 1]), 0.f);
    float r2 = x4.z + fmaxf(fmaf(h4.z, sc[o + 2], sh[o + 2]), 0.f);
    float r3 = x4.w + fmaxf(fmaf(h4.w, sc[o + 3], sh[o + 3]), 0.f);
    *(float4*)(x + idx) = make_float4(r0, r1, r2, r3);
    __half2 p0 = __floats2half2_rn(r0, r1);
    __half2 p1 = __floats2half2_rn(r2, r3);
    uint2 pk;
    pk.x = *(unsigned*)&p0;
    pk.y = *(unsigned*)&p1;
    int c = 16 + (o >> 6);
    char* p = (char*)g_A + ((size_t)c * NN + n) * 128 +
              (((uint32_t)((o & 63) * 2)) ^ ((n & 7) << 4));
    *(uint2*)p = pk;
}

// ---------------- launch -----------------------------------------------------

extern "C" void kernel_launch(void* const* d_in, const int* in_sizes, int n_in,
                              void* d_out, int out_size) {
    const int* x_ids = (const int*)d_in[0];
    const int* edge_index = (const int*)d_in[1];
    const int* edge_type = (const int*)d_in[2];
    const float* node_feat = (const float*)d_in[3];
    const float* emb = (const float*)d_in[4];
    const float* feat_w = (const float*)d_in[5];
    const float* feat_b = (const float*)d_in[6];
    const float* virt = (const float*)d_in[7];
    const float* bases = (const float*)d_in[8];
    const float* comp = (const float*)d_in[9];
    const float* root = (const float*)d_in[10];
    const float* bias = (const float*)d_in[11];
    const float* gamma = (const float*)d_in[12];
    const float* beta = (const float*)d_in[13];
    float* x = (float*)d_out;

    const int GEMM_SMEM = 4096 + NST * STAGE_BYTES;   // 102400
    static int attr_set = 0;
    if (!attr_set) {
        cudaFuncSetAttribute(gemm_kernel,
                             cudaFuncAttributeMaxDynamicSharedMemorySize, GEMM_SMEM);
        attr_set = 1;
    }

    init_x_kernel<<<NN, HH>>>(x, x_ids, node_feat, emb, feat_w, feat_b, virt);
    count_edges_kernel<<<(EE + 255) / 256, 256>>>(edge_index, edge_type);
    scan_block_kernel<<<NBLK, 1024>>>();
    scan_sums_kernel<<<1, 512>>>();
    csr_fill_kernel<<<(EE + 255) / 256, 256>>>(edge_index, edge_type);

    for (int l = 0; l < LL; l++) {
        build_W_kernel<<<HH, 256>>>(comp, bases, root, l);
        seg_sum_kernel<<<(NSEG + 7) / 8, 256>>>();
        gemm_kernel<<<(NN + 127) / 128, 256, GEMM_SMEM>>>(bias + l * HH);
        update_kernel<<<NN * HH / 1024, 256>>>(x, gamma + l * HH, beta + l * HH);
    }
}

// round 14
// speedup vs baseline: 1.2248x; 1.2248x over previous
#include <cuda_runtime.h>
#include <cuda_fp16.h>
#include <stdint.h>

#define NN 50000
#define EE 800000
#define RR 8
#define BB 8
#define HH 128
#define LL 3
#define FDIM 6
#define KTOT 1152          // R*H + H (root folded in)
#define NSEG (NN * RR)     // 400000
#define NBLK 391           // ceil(NSEG/1024)
#define BN_EPS 1e-5f
#define NST 3              // GEMM pipeline stages (measured-good config)
#define KC 64              // K-chunk in halves (128B rows)
#define NKT (KTOT / KC)    // 18 chunks
#define STAGE_BYTES 32768  // A 16KB + B 16KB

// ---------------- scratch (static device memory) ----------------------------
// Tiled + pre-swizzled A: [chunk][n][64 halves]; element (n,k) at plane k/64,
// row n, byte ((k&63)*2) ^ ((n&7)<<4).  Chunks 0..15 = seg means, 16..17 = x.
__device__ __half g_A[(size_t)NKT * NN * KC + 8192];   // 115.2 MB + pad
__device__ __half g_WhT[NKT * HH * KC];                // tiled+swizzled W
__device__ float  g_h[NN * HH];                        // pre-BN layer output
__device__ int    g_cnt[NSEG];
__device__ int    g_off[NSEG + 1];                     // block-local exclusive partials
__device__ int    g_cursor[NSEG];
__device__ int    g_bsum[512];                         // exclusive block offsets
__device__ int    g_src[EE];
__device__ double g_sum[HH], g_sumsq[HH];

// ---------------- PTX helpers -------------------------------------------------
#define MBARRIER_INIT(addr, cnt) \
    asm volatile("mbarrier.init.shared.b64 [%0], %1;" :: "r"(addr), "r"(cnt) : "memory")
#define MBARRIER_EXPECT_TX(addr, bytes) \
    asm volatile("mbarrier.arrive.expect_tx.shared.b64 _, [%0], %1;" \
                 :: "r"(addr), "r"(bytes) : "memory")
#define MBARRIER_WAIT_PARITY(addr, par) do {                                   \
    asm volatile(                                                              \
        "{\n\t.reg .pred P1;\n\t"                                              \
        "WAIT_LOOP_%=:\n\t"                                                    \
        "mbarrier.try_wait.parity.acquire.cta.shared::cta.b64 P1, [%0], %1, 0x989680;\n\t" \
        "@P1 bra.uni WAIT_DONE_%=;\n\t"                                        \
        "bra.uni WAIT_LOOP_%=;\n\t"                                            \
        "WAIT_DONE_%=:\n\t}"                                                   \
        :: "r"(addr), "r"(par) : "memory");                                    \
} while (0)
#define BULK_G2S(dst_u32, src, bytes, mbar) \
    asm volatile("cp.async.bulk.shared::cluster.global.mbarrier::complete_tx::bytes " \
                 "[%0], [%1], %2, [%3];" \
                 :: "r"(dst_u32), "l"(src), "r"(bytes), "r"(mbar) : "memory")

// swizzled byte-offset within a 128B row
__device__ __forceinline__ uint32_t swz(int row, int hcol) {
    return (uint32_t)((hcol * 2) ^ ((row & 7) << 4));
}

// ---------------- init / CSR build ------------------------------------------

__global__ void init_x_kernel(float* __restrict__ x,
                              const int* __restrict__ x_ids,
                              const float* __restrict__ node_feat,
                              const float* __restrict__ emb,
                              const float* __restrict__ feat_w,
                              const float* __restrict__ feat_b,
                              const float* __restrict__ virt) {
    int n = blockIdx.x, o = threadIdx.x;
    int gt = blockIdx.x * blockDim.x + threadIdx.x;
    if (gt < NSEG) g_cnt[gt] = 0;
    float f = feat_b[o];
#pragma unroll
    for (int d = 0; d < FDIM; d++)
        f += node_feat[n * FDIM + d] * feat_w[o * FDIM + d];
    float v = emb[x_ids[n] * HH + o] + fmaxf(f, 0.f) + virt[o];
    x[n * HH + o] = v;
    int c = 16 + (o >> 6);
    char* p = (char*)g_A + ((size_t)c * NN + n) * 128 + swz(n, o & 63);
    *(__half*)p = __float2half(v);
}

__global__ void count_edges_kernel(const int* __restrict__ edge_index,
                                   const int* __restrict__ edge_type) {
    int e = blockIdx.x * blockDim.x + threadIdx.x;
    if (e >= EE) return;
    atomicAdd(&g_cnt[edge_index[EE + e] * RR + edge_type[e]], 1);
}

__global__ void scan_block_kernel() {
    __shared__ int sm[1024];
    int i = blockIdx.x * 1024 + threadIdx.x;
    int v = (i < NSEG) ? g_cnt[i] : 0;
    sm[threadIdx.x] = v;
    __syncthreads();
    for (int s = 1; s < 1024; s <<= 1) {
        int t = (threadIdx.x >= s) ? sm[threadIdx.x - s] : 0;
        __syncthreads();
        sm[threadIdx.x] += t;
        __syncthreads();
    }
    if (i < NSEG) {
        int o = sm[threadIdx.x] - v;     // block-local exclusive
        g_off[i] = o;
        g_cursor[i] = o;
    }
    if (threadIdx.x == 1023) g_bsum[blockIdx.x] = sm[1023];
}

__global__ void scan_sums_kernel() {
    __shared__ int sm[512];
    int v = (threadIdx.x < NBLK) ? g_bsum[threadIdx.x] : 0;
    sm[threadIdx.x] = v;
    __syncthreads();
    for (int s = 1; s < 512; s <<= 1) {
        int t = (threadIdx.x >= s) ? sm[threadIdx.x - s] : 0;
        __syncthreads();
        sm[threadIdx.x] += t;
        __syncthreads();
    }
    g_bsum[threadIdx.x] = sm[threadIdx.x] - v;   // exclusive block offsets
}

// final position = local cursor + block offset
__global__ void csr_fill_kernel(const int* __restrict__ edge_index,
                                const int* __restrict__ edge_type) {
    int e = blockIdx.x * blockDim.x + threadIdx.x;
    if (e >= EE) return;
    int seg = edge_index[EE + e] * RR + edge_type[e];
    int pos = atomicAdd(&g_cursor[seg], 1) + g_bsum[seg >> 10];
    g_src[pos] = edge_index[e];
}

// ---------------- per-layer kernels -----------------------------------------

// W tiled+swizzled + zero BN stats.
__global__ void build_W_kernel(const float* __restrict__ comp,
                               const float* __restrict__ bases,
                               const float* __restrict__ root, int l) {
    int o = blockIdx.x;
    if (threadIdx.x == 0) { g_sum[o] = 0.0; g_sumsq[o] = 0.0; }
    for (int k = threadIdx.x; k < KTOT; k += blockDim.x) {
        float acc;
        if (k < RR * HH) {
            int r = k >> 7, i = k & 127;
            acc = 0.f;
#pragma unroll
            for (int b = 0; b < BB; b++)
                acc += comp[(l * RR + r) * BB + b] *
                       bases[((l * BB + b) * HH + i) * HH + o];
        } else {
            acc = root[(l * HH + (k - RR * HH)) * HH + o];
        }
        int c = k >> 6;
        char* p = (char*)g_WhT + ((size_t)c * HH + o) * 128 + swz(o, k & 63);
        *(__half*)p = __float2half(acc);
    }
}

// 16-lane sub-warp per segment (16 segs/block), uint4 gathers, src prefetch.
// Reads x planes (16,17); writes mean planes (2r, 2r+1). Same element-wise
// arithmetic as the 32-lane version -> bit-identical output.
__global__ void seg_sum_kernel() {
    int seg = blockIdx.x * 16 + (threadIdx.x >> 4);
    if (seg >= NSEG) return;
    int l16 = threadIdx.x & 15;
    int cx = 16 + (l16 >> 3);                      // source x plane
    uint32_t bcol = (uint32_t)((l16 & 7) * 16);    // 16B column
    int beg = g_off[seg] + g_bsum[seg >> 10];
    int cnt = g_cnt[seg];
    int end = beg + cnt;
    float a0 = 0.f, a1 = 0.f, a2 = 0.f, a3 = 0.f;
    float a4 = 0.f, a5 = 0.f, a6 = 0.f, a7 = 0.f;
    const char* xbase = (const char*)g_A + (size_t)cx * NN * 128;
    int nx = (cnt > 0) ? g_src[beg] : 0;
    for (int e = beg; e < end; e++) {
        int src = nx;
        if (e + 1 < end) nx = g_src[e + 1];        // prefetch next index
        uint4 v = *(const uint4*)(xbase + (size_t)src * 128 + (bcol ^ ((src & 7) << 4)));
        float2 f0 = __half22float2(*(__half2*)&v.x);
        float2 f1 = __half22float2(*(__half2*)&v.y);
        float2 f2 = __half22float2(*(__half2*)&v.z);
        float2 f3 = __half22float2(*(__half2*)&v.w);
        a0 += f0.x; a1 += f0.y; a2 += f1.x; a3 += f1.y;
        a4 += f2.x; a5 += f2.y; a6 += f3.x; a7 += f3.y;
    }
    float inv = (cnt > 0) ? 1.f / (float)cnt : 0.f;
    __half2 o0 = __floats2half2_rn(a0 * inv, a1 * inv);
    __half2 o1 = __floats2half2_rn(a2 * inv, a3 * inv);
    __half2 o2 = __floats2half2_rn(a4 * inv, a5 * inv);
    __half2 o3 = __floats2half2_rn(a6 * inv, a7 * inv);
    uint4 o;
    o.x = *(unsigned*)&o0;
    o.y = *(unsigned*)&o1;
    o.z = *(unsigned*)&o2;
    o.w = *(unsigned*)&o3;
    int n = seg >> 3, r = seg & 7;
    int cd = 2 * r + (l16 >> 3);
    char* dst = (char*)g_A + ((size_t)cd * NN + n) * 128 + (bcol ^ ((n & 7) << 4));
    *(uint4*)dst = o;
}

// GEMM: g_h = A[50000 x 1152] * W[1152 x 128] + bias, BN stats fused.
// Bulk-async loads (2 per stage), 3 stages, mma.sync m16n8k16 fp32-acc.
// Identical to the R9 measured-good configuration.
__global__ void __launch_bounds__(256) gemm_kernel(const float* __restrict__ bias) {
    extern __shared__ __align__(1024) char dynsm[];
    uint32_t smem_base;
    asm("{ .reg .u64 t; cvta.to.shared.u64 t, %1; cvt.u32.u64 %0, t; }"
        : "=r"(smem_base) : "l"(dynsm));
    const uint32_t MBAR = smem_base;           // 3 x 8B
    float* red = (float*)(dynsm + 64);          // [2][128][2] = 2KB
    char* stages = dynsm + 4096;
    const uint32_t STAGES_U32 = smem_base + 4096;

    int tid = threadIdx.x;
    int warp = tid >> 5, lane = tid & 31;
    int warp_m = warp >> 2, warp_n = warp & 3;   // 2 x 4 warps
    int m0 = blockIdx.x * 128;
    int gr = lane >> 2, tc = lane & 3;

    if (tid == 0) {
#pragma unroll
        for (int s = 0; s < NST; s++) MBARRIER_INIT(MBAR + s * 8, 1);
    }
    __syncthreads();

    // prologue: issue chunks 0..NST-1
    if (tid == 0) {
#pragma unroll
        for (int s = 0; s < NST; s++) {
            MBARRIER_EXPECT_TX(MBAR + s * 8, STAGE_BYTES);
            const char* srcA = (const char*)g_A + ((size_t)s * NN + m0) * 128;
            const char* srcB = (const char*)g_WhT + (size_t)s * HH * 128;
            BULK_G2S(STAGES_U32 + s * STAGE_BYTES, srcA, 16384, MBAR + s * 8);
            BULK_G2S(STAGES_U32 + s * STAGE_BYTES + 16384, srcB, 16384, MBAR + s * 8);
        }
    }

    float acc[4][4][4];
#pragma unroll
    for (int a = 0; a < 4; a++)
#pragma unroll
        for (int b = 0; b < 4; b++)
#pragma unroll
            for (int c = 0; c < 4; c++) acc[a][b][c] = 0.f;

    for (int t = 0; t < NKT; t++) {
        int s = t % NST;
        MBARRIER_WAIT_PARITY(MBAR + s * 8, (t / NST) & 1);

        const char* sA = stages + s * STAGE_BYTES;
        const char* sB = sA + 16384;
#pragma unroll
        for (int kk = 0; kk < KC; kk += 16) {
            int hc0 = kk + 2 * tc;
            unsigned bf[4][2];
#pragma unroll
            for (int nt = 0; nt < 4; nt++) {
                int n0 = warp_n * 32 + nt * 8 + gr;
                const char* bp = sB + n0 * 128;
                bf[nt][0] = *(const unsigned*)(bp + swz(n0, hc0));
                bf[nt][1] = *(const unsigned*)(bp + swz(n0, hc0 + 8));
            }
#pragma unroll
            for (int mt = 0; mt < 4; mt++) {
                int r0 = warp_m * 64 + mt * 16 + gr;
                const char* ap0 = sA + r0 * 128;
                const char* ap1 = sA + (r0 + 8) * 128;
                unsigned a0 = *(const unsigned*)(ap0 + swz(r0, hc0));
                unsigned a1 = *(const unsigned*)(ap1 + swz(r0 + 8, hc0));
                unsigned a2 = *(const unsigned*)(ap0 + swz(r0, hc0 + 8));
                unsigned a3 = *(const unsigned*)(ap1 + swz(r0 + 8, hc0 + 8));
#pragma unroll
                for (int nt = 0; nt < 4; nt++) {
                    asm volatile(
                        "mma.sync.aligned.m16n8k16.row.col.f32.f16.f16.f32 "
                        "{%0,%1,%2,%3}, {%4,%5,%6,%7}, {%8,%9}, {%0,%1,%2,%3};\n"
                        : "+f"(acc[mt][nt][0]), "+f"(acc[mt][nt][1]),
                          "+f"(acc[mt][nt][2]), "+f"(acc[mt][nt][3])
                        : "r"(a0), "r"(a1), "r"(a2), "r"(a3),
                          "r"(bf[nt][0]), "r"(bf[nt][1]));
                }
            }
        }
        __syncthreads();
        if (tid == 0 && t + NST < NKT) {
            int u = t + NST;
            MBARRIER_EXPECT_TX(MBAR + s * 8, STAGE_BYTES);
            const char* srcA = (const char*)g_A + ((size_t)u * NN + m0) * 128;
            const char* srcB = (const char*)g_WhT + (size_t)u * HH * 128;
            BULK_G2S(STAGES_U32 + s * STAGE_BYTES, srcA, 16384, MBAR + s * 8);
            BULK_G2S(STAGES_U32 + s * STAGE_BYTES + 16384, srcB, 16384, MBAR + s * 8);
        }
    }

    // epilogue: + bias, store fp32, BN stats
    float s4[4][2] = {}, q4[4][2] = {};
#pragma unroll
    for (int mt = 0; mt < 4; mt++) {
#pragma unroll
        for (int nt = 0; nt < 4; nt++) {
            int row = m0 + warp_m * 64 + mt * 16 + gr;
            int col = warp_n * 32 + nt * 8 + 2 * tc;
            float b0 = bias[col], b1 = bias[col + 1];
            if (row < NN) {
                float h0 = acc[mt][nt][0] + b0;
                float h1 = acc[mt][nt][1] + b1;
                g_h[row * HH + col] = h0;
                g_h[row * HH + col + 1] = h1;
                s4[nt][0] += h0; q4[nt][0] += h0 * h0;
                s4[nt][1] += h1; q4[nt][1] += h1 * h1;
            }
            if (row + 8 < NN) {
                float h2 = acc[mt][nt][2] + b0;
                float h3 = acc[mt][nt][3] + b1;
                g_h[(row + 8) * HH + col] = h2;
                g_h[(row + 8) * HH + col + 1] = h3;
                s4[nt][0] += h2; q4[nt][0] += h2 * h2;
                s4[nt][1] += h3; q4[nt][1] += h3 * h3;
            }
        }
    }
#pragma unroll
    for (int nt = 0; nt < 4; nt++) {
#pragma unroll
        for (int idx = 0; idx < 2; idx++) {
            float v = s4[nt][idx], w = q4[nt][idx];
#pragma unroll
            for (int off = 16; off >= 4; off >>= 1) {
                v += __shfl_down_sync(0xffffffffu, v, off);
                w += __shfl_down_sync(0xffffffffu, w, off);
            }
            if (gr == 0) {
                int col = warp_n * 32 + nt * 8 + 2 * tc + idx;
                red[(warp_m * 128 + col) * 2 + 0] = v;
                red[(warp_m * 128 + col) * 2 + 1] = w;
            }
        }
    }
    __syncthreads();
    if (tid < 128) {
        int col = tid;
        atomicAdd(&g_sum[col],   (double)(red[col * 2] + red[(128 + col) * 2]));
        atomicAdd(&g_sumsq[col], (double)(red[col * 2 + 1] + red[(128 + col) * 2 + 1]));
    }
}

// update: BN scale/shift computed per block, 4 elements per thread.
__global__ void update_kernel(float* __restrict__ x,
                              const float* __restrict__ gamma,
                              const float* __restrict__ beta) {
    __shared__ float sc[HH], sh[HH];
    int t = threadIdx.x;
    if (t < HH) {
        const double invN = 1.0 / (double)NN;
        double mu = g_sum[t] * invN;
        double var = g_sumsq[t] * invN - mu * mu;
        float rstd = rsqrtf((float)var + BN_EPS);
        float s = gamma[t] * rstd;
        sc[t] = s;
        sh[t] = beta[t] - (float)mu * s;
    }
    __syncthreads();
    int idx = (blockIdx.x * 256 + t) * 4;
    int n = idx >> 7, o = idx & 127;
    float4 h4 = *(const float4*)(g_h + idx);
    float4 x4 = *(float4*)(x + idx);
    float r0 = x4.x + fmaxf(fmaf(h4.x, sc[o],     sh[o]),     0.f);
    float r1 = x4.y + fmaxf(fmaf(h4.y, sc[o + 1], sh[o + 1]), 0.f);
    float r2 = x4.z + fmaxf(fmaf(h4.z, sc[o + 2], sh[o + 2]), 0.f);
    float r3 = x4.w + fmaxf(fmaf(h4.w, sc[o + 3], sh[o + 3]), 0.f);
    *(float4*)(x + idx) = make_float4(r0, r1, r2, r3);
    __half2 p0 = __floats2half2_rn(r0, r1);
    __half2 p1 = __floats2half2_rn(r2, r3);
    uint2 pk;
    pk.x = *(unsigned*)&p0;
    pk.y = *(unsigned*)&p1;
    int c = 16 + (o >> 6);
    char* p = (char*)g_A + ((size_t)c * NN + n) * 128 +
              (((uint32_t)((o & 63) * 2)) ^ ((n & 7) << 4));
    *(uint2*)p = pk;
}

// ---------------- launch -----------------------------------------------------

extern "C" void kernel_launch(void* const* d_in, const int* in_sizes, int n_in,
                              void* d_out, int out_size) {
    const int* x_ids = (const int*)d_in[0];
    const int* edge_index = (const int*)d_in[1];
    const int* edge_type = (const int*)d_in[2];
    const float* node_feat = (const float*)d_in[3];
    const float* emb = (const float*)d_in[4];
    const float* feat_w = (const float*)d_in[5];
    const float* feat_b = (const float*)d_in[6];
    const float* virt = (const float*)d_in[7];
    const float* bases = (const float*)d_in[8];
    const float* comp = (const float*)d_in[9];
    const float* root = (const float*)d_in[10];
    const float* bias = (const float*)d_in[11];
    const float* gamma = (const float*)d_in[12];
    const float* beta = (const float*)d_in[13];
    float* x = (float*)d_out;

    const int GEMM_SMEM = 4096 + NST * STAGE_BYTES;   // 102400
    static int attr_set = 0;
    if (!attr_set) {
        cudaFuncSetAttribute(gemm_kernel,
                             cudaFuncAttributeMaxDynamicSharedMemorySize, GEMM_SMEM);
        attr_set = 1;
    }

    init_x_kernel<<<NN, HH>>>(x, x_ids, node_feat, emb, feat_w, feat_b, virt);
    count_edges_kernel<<<(EE + 255) / 256, 256>>>(edge_index, edge_type);
    scan_block_kernel<<<NBLK, 1024>>>();
    scan_sums_kernel<<<1, 512>>>();
    csr_fill_kernel<<<(EE + 255) / 256, 256>>>(edge_index, edge_type);

    for (int l = 0; l < LL; l++) {
        build_W_kernel<<<HH, 256>>>(comp, bases, root, l);
        seg_sum_kernel<<<(NSEG + 15) / 16, 256>>>();
        gemm_kernel<<<(NN + 127) / 128, 256, GEMM_SMEM>>>(bias + l * HH);
        update_kernel<<<NN * HH / 1024, 256>>>(x, gamma + l * HH, beta + l * HH);
    }
}